// round 16
// baseline (speedup 1.0000x reference)
#include <cuda_runtime.h>
#include <cuda_bf16.h>
#include <cstdint>

typedef uint32_t u32;

// Pre-split transposed weights: Wt[n][k] bf16 hi/lo, row-major [256][256] (512B rows).
__device__ __align__(16) unsigned char g_Wh[3][131072];
__device__ __align__(16) unsigned char g_Wl[3][131072];

// ---- smem byte map (regions XOR-swizzled: 16B-unit col ^= (row & 7)) ----
#define XH_B   0             // X hi [128 rows][512B]
#define WB_B   65536         // 3 W buffers, each: hi[32][512B] + lo[32][512B] = 32K
#define WBUF_SZ 32768
#define QH_B   163840        // Q hi [128 rows][128B]   (phase B: Vt hi [64 rows][256B])
#define QL_B   180224        // Q lo                    (phase B: Vt lo)
#define KH_B   196608        // K hi [128 rows][128B]
#define KL_B   212992        // K lo
#define SMEM_B 229376

#define MMA(d, a0, a1, a2, a3, b0, b1) \
    asm volatile("mma.sync.aligned.m16n8k16.row.col.f32.bf16.bf16.f32 " \
        "{%0,%1,%2,%3},{%4,%5,%6,%7},{%8,%9},{%0,%1,%2,%3};" \
        : "+f"((d)[0]), "+f"((d)[1]), "+f"((d)[2]), "+f"((d)[3]) \
        : "r"(a0), "r"(a1), "r"(a2), "r"(a3), "r"(b0), "r"(b1))

#define LDSM4(r0, r1, r2, r3, a) \
    asm volatile("ldmatrix.sync.aligned.m8n8.x4.shared.b16 {%0,%1,%2,%3}, [%4];" \
        : "=r"(r0), "=r"(r1), "=r"(r2), "=r"(r3) : "r"(a))

#define CPA16(dst, src) \
    asm volatile("cp.async.cg.shared.global [%0], [%1], 16;" :: "r"(dst), "l"(src))
#define CPC()  asm volatile("cp.async.commit_group;")
#define CPW1() asm volatile("cp.async.wait_group 1;")

__device__ __forceinline__ void split2(float f0, float f1, u32& hp, u32& lp) {
    asm("cvt.rn.bf16x2.f32 %0, %1, %2;" : "=r"(hp) : "f"(f1), "f"(f0));
    float h0 = __uint_as_float(hp << 16);
    float h1 = __uint_as_float(hp & 0xffff0000u);
    asm("cvt.rn.bf16x2.f32 %0, %1, %2;" : "=r"(lp) : "f"(f1 - h1), "f"(f0 - h0));
}

// ---------------- prep: transpose + split weights ----------------
__global__ void prep_w(const float* __restrict__ wq, const float* __restrict__ wk,
                       const float* __restrict__ wv)
{
    int idx = blockIdx.x * blockDim.x + threadIdx.x;
    if (idx >= 3 * 65536) return;
    int w = idx >> 16, e = idx & 65535;
    int k = e >> 8, n = e & 255;
    const float* W = (w == 0) ? wq : (w == 1) ? wk : wv;
    float f = W[k * 256 + n];
    __nv_bfloat16 h = __float2bfloat16(f);
    __nv_bfloat16 l = __float2bfloat16(f - __bfloat162float(h));
    *(__nv_bfloat16*)(g_Wh[w] + n * 512 + k * 2) = h;   // Wt[n][k]
    *(__nv_bfloat16*)(g_Wl[w] + n * 512 + k * 2) = l;
}

// prefetch one half-chunk (32 n rows, hi+lo) into a W buffer, swizzled.
__device__ __forceinline__ void pf_half(int idx, u32 dst, int tid) {
    int wsel, row0;
    if (idx < 16) { wsel = (idx >> 1) & 1; row0 = (idx >> 2) * 64 + (idx & 1) * 32; }
    else { int j = idx - 16; wsel = 2; row0 = (j >> 1) * 64 + (j & 1) * 32; }
    const unsigned char* gh = g_Wh[wsel] + row0 * 512;
    const unsigned char* gl = g_Wl[wsel] + row0 * 512;
#pragma unroll
    for (int i = 0; i < 4; i++) {
        int e = tid + i * 256;               // 0..1023: 32 rows x 32 units
        int r = e >> 5, c = e & 31;
        u32 so = (u32)(r * 512 + ((c ^ (r & 7)) << 4));
        CPA16(dst + so, gh + r * 512 + c * 16);
        CPA16(dst + 16384 + so, gl + r * 512 + c * 16);
    }
    CPC();
}

// one half projection pass; software-pipelined fragments (one kk lookahead).
#define RUNHALF(ACC, JB) do {                                                   \
    CPW1(); __syncthreads();                                                    \
    if (nextpf < 24) pf_half(nextpf, wbuf[nextpf % 3], tid); else CPC();        \
    nextpf++;                                                                   \
    u32 wbase = wAddrT + (u32)cur * WBUF_SZ;                                    \
    cur = (cur == 2) ? 0 : cur + 1;                                             \
    u32 AH0[2], AH1[2], AH2[2], AH3[2];                                         \
    u32 WB0[2][4], WB1[2][4], WC0[2][4], WC1[2][4];                             \
    {   u32 k0 = (u32)((0 ^ txe) << 4);                                         \
        LDSM4(AH0[0], AH1[0], AH2[0], AH3[0], aXH + k0);                        \
        _Pragma("unroll")                                                       \
        for (int j = 0; j < 4; j++)                                             \
            LDSM4(WB0[0][j], WB1[0][j], WC0[0][j], WC1[0][j],                   \
                  wbase + (u32)(j * 4096) + k0);                                \
    }                                                                           \
    _Pragma("unroll")                                                           \
    for (int kk = 0; kk < 16; kk++) {                                           \
        int p = kk & 1, nx = p ^ 1;                                             \
        if (kk < 15) {                                                          \
            u32 kn = (u32)((((kk + 1) * 2) ^ txe) << 4);                        \
            LDSM4(AH0[nx], AH1[nx], AH2[nx], AH3[nx], aXH + kn);                \
            _Pragma("unroll")                                                   \
            for (int j = 0; j < 4; j++)                                         \
                LDSM4(WB0[nx][j], WB1[nx][j], WC0[nx][j], WC1[nx][j],           \
                      wbase + (u32)(j * 4096) + kn);                            \
        }                                                                       \
        _Pragma("unroll")                                                       \
        for (int j = 0; j < 4; j++)                                             \
            MMA(ACC[(JB) + j], AH0[p], AH1[p], AH2[p], AH3[p], WB0[p][j], WB1[p][j]); \
        _Pragma("unroll")                                                       \
        for (int j = 0; j < 4; j++)                                             \
            MMA(ACC[(JB) + j], alo[kk][0], alo[kk][1], alo[kk][2], alo[kk][3], WB0[p][j], WB1[p][j]); \
        _Pragma("unroll")                                                       \
        for (int j = 0; j < 4; j++)                                             \
            MMA(ACC[(JB) + j], AH0[p], AH1[p], AH2[p], AH3[p], WC0[p][j], WC1[p][j]); \
    }                                                                           \
} while (0)

__global__ void __launch_bounds__(256, 1)
attn_mma_kernel(const float* __restrict__ x,
                const float* __restrict__ bq, const float* __restrict__ bk,
                const float* __restrict__ bv, float* __restrict__ out)
{
    extern __shared__ char smc[];
    u32 smb;
    asm("{ .reg .u64 t; cvta.to.shared.u64 t, %1; cvt.u32.u64 %0, t; }" : "=r"(smb) : "l"(smc));

    const int tid = threadIdx.x;
    const int w = tid >> 5, t = tid & 31;
    const int qd = t >> 2, tq = t & 3;
    const int R = w * 16;                 // warp's 16 stacked rows
    const int bh64 = (w >> 2) * 64;       // 0 (bh0) or 64 (bh1)

    // ldmatrix thread-role decomposition
    const int tm8 = t & 7;
    const int g8  = (t >> 3) & 1;
    const int g16 = t >> 4;
    const int txe = tm8 & 6, txo = tm8 & 1;

    const float* xg = x + (size_t)blockIdx.x * 32768;
    float*       og = out + (size_t)blockIdx.x * 32768;

    u32* qh = (u32*)(smc + QH_B);
    u32* ql = (u32*)(smc + QL_B);
    u32* kh = (u32*)(smc + KH_B);
    u32* kl = (u32*)(smc + KL_B);

    // ---- stage X: hi -> XH, lo -> WB region (temp), both swizzled ----
    {
        int row = tid >> 1, khf = (tid & 1) * 128;
        const float4* src = (const float4*)(xg + row * 256 + khf);
        int rx = row & 7;
        char* dh = smc + XH_B + row * 512;
        char* dl = smc + WB_B + row * 512;
#pragma unroll 8
        for (int j2 = 0; j2 < 32; j2++) {
            float4 v = src[j2];
            int unit = (khf >> 3) + (j2 >> 1);
            u32 off = (u32)(((unit ^ rx) << 4) + ((j2 & 1) << 3));
            u32 h0, l0, h1, l1;
            split2(v.x, v.y, h0, l0);
            split2(v.z, v.w, h1, l1);
            *(u32*)(dh + off) = h0; *(u32*)(dh + off + 4) = h1;
            *(u32*)(dl + off) = l0; *(u32*)(dl + off + 4) = l1;
        }
    }
    __syncthreads();

    // ---- A-lo fragments -> registers via ldmatrix ----
    const u32 aXH = smb + XH_B + (u32)(R + tm8 + 8 * g8) * 512 + (u32)((g16 ^ txo) << 4);
    u32 alo[16][4];
    {
        const u32 aXLt = smb + WB_B + (u32)(R + tm8 + 8 * g8) * 512 + (u32)((g16 ^ txo) << 4);
#pragma unroll
        for (int kk = 0; kk < 16; kk++) {
            u32 koff = (u32)(((kk * 2) ^ txe) << 4);
            LDSM4(alo[kk][0], alo[kk][1], alo[kk][2], alo[kk][3], aXLt + koff);
        }
    }
    __syncthreads();

    // ---- per-thread ldmatrix base addresses ----
    const u32 wAddrT = smb + WB_B + (u32)g16 * 16384 + (u32)tm8 * 512 + (u32)((g8 ^ txo) << 4);
    const u32 qAddrT = smb + QH_B + (u32)g16 * 16384 + (u32)(bh64 + tm8) * 128 + (u32)((g8 ^ txo) << 4);
    const u32 vAddrT = smb + QH_B + (u32)g16 * 16384 + (u32)tm8 * 256 + (u32)((bh64 >> 3) << 4) + (u32)((g8 ^ txo) << 4);
    // K-as-A fragment reads (row-major, same pattern as aXH but 128B rows)
    const u32 kAh = smb + KH_B + (u32)(R + tm8 + 8 * g8) * 128 + (u32)((g16 ^ txo) << 4);
    const u32 kAl = kAh + 16384;

    // ---- prime the W pipeline (3 rotating buffers) ----
    u32 wbuf[3] = { smb + WB_B, smb + WB_B + WBUF_SZ, smb + WB_B + 2 * WBUF_SZ };
    pf_half(0, wbuf[0], tid);
    pf_half(1, wbuf[1], tid);
    int nextpf = 2, cur = 0;

    float S[8][4];
#pragma unroll
    for (int j = 0; j < 8; j++) { S[j][0] = S[j][1] = S[j][2] = S[j][3] = 0.f; }

    // ================= phase A: Q,K proj + S accumulation =================
    for (int cc = 0; cc < 4; cc++) {
        float acc[8][4];
        // ---- Q projection ----
#pragma unroll
        for (int j = 0; j < 8; j++) { acc[j][0] = acc[j][1] = acc[j][2] = acc[j][3] = 0.f; }
        RUNHALF(acc, 0);
        RUNHALF(acc, 4);
        {   // Q epilogue: +bias, split, swizzled store [row][128B]
            const float* bias = bq + cc * 64;
            int r0 = R + qd;
#pragma unroll
            for (int j = 0; j < 8; j++) {
                float2 bb = *(const float2*)(bias + 8 * j + tq * 2);
                int wo = ((j ^ qd) << 2) + tq;
                u32 hp, lp;
                split2(acc[j][0] + bb.x, acc[j][1] + bb.y, hp, lp);
                qh[r0 * 32 + wo] = hp; ql[r0 * 32 + wo] = lp;
                split2(acc[j][2] + bb.x, acc[j][3] + bb.y, hp, lp);
                qh[(r0 + 8) * 32 + wo] = hp; ql[(r0 + 8) * 32 + wo] = lp;
            }
        }
        // ---- K projection ----
#pragma unroll
        for (int j = 0; j < 8; j++) { acc[j][0] = acc[j][1] = acc[j][2] = acc[j][3] = 0.f; }
        RUNHALF(acc, 0);
        RUNHALF(acc, 4);
        {   // K epilogue: +bias, split, swizzled store to K buffers
            const float* bias = bk + cc * 64;
            int r0 = R + qd;
#pragma unroll
            for (int j = 0; j < 8; j++) {
                float2 bb = *(const float2*)(bias + 8 * j + tq * 2);
                int wo = ((j ^ qd) << 2) + tq;
                u32 hp, lp;
                split2(acc[j][0] + bb.x, acc[j][1] + bb.y, hp, lp);
                kh[r0 * 32 + wo] = hp; kl[r0 * 32 + wo] = lp;
                split2(acc[j][2] + bb.x, acc[j][3] + bb.y, hp, lp);
                kh[(r0 + 8) * 32 + wo] = hp; kl[(r0 + 8) * 32 + wo] = lp;
            }
        }
        __syncthreads();   // K (and Q) visible before S-GEMM reads
        // ---- S += Kc * Qc^T  (A = K smem, B = Q smem; pipelined groups) ----
        {
            u32 kfh[4][4], kfl[4][4];
#pragma unroll
            for (int kk = 0; kk < 4; kk++) {
                u32 ko = (u32)(((kk * 2) ^ txe) << 4);
                LDSM4(kfh[kk][0], kfh[kk][1], kfh[kk][2], kfh[kk][3], kAh + ko);
                LDSM4(kfl[kk][0], kfl[kk][1], kfl[kk][2], kfl[kk][3], kAl + ko);
            }
            u32 QB0[2][4], QB1[2][4], QC0[2][4], QC1[2][4];
            {
                u32 ko = (u32)((0 ^ txe) << 4);
#pragma unroll
                for (int j = 0; j < 4; j++)
                    LDSM4(QB0[0][j], QB1[0][j], QC0[0][j], QC1[0][j], qAddrT + (u32)(j * 1024) + ko);
            }
#pragma unroll
            for (int g = 0; g < 8; g++) {     // g = kk*2 + jg-half
                int p = g & 1, nx = p ^ 1;
                if (g < 7) {
                    int g2 = g + 1;
                    int kk2 = g2 >> 1, jb2 = (g2 & 1) * 4;
                    u32 ko2 = (u32)(((kk2 * 2) ^ txe) << 4);
#pragma unroll
                    for (int j = 0; j < 4; j++)
                        LDSM4(QB0[nx][j], QB1[nx][j], QC0[nx][j], QC1[nx][j],
                              qAddrT + (u32)((jb2 + j) * 1024) + ko2);
                }
                int kk = g >> 1, jb = (g & 1) * 4;
#pragma unroll
                for (int j = 0; j < 4; j++)
                    MMA(S[jb + j], kfh[kk][0], kfh[kk][1], kfh[kk][2], kfh[kk][3], QB0[p][j], QB1[p][j]);
#pragma unroll
                for (int j = 0; j < 4; j++)
                    MMA(S[jb + j], kfh[kk][0], kfh[kk][1], kfh[kk][2], kfh[kk][3], QC0[p][j], QC1[p][j]);
#pragma unroll
                for (int j = 0; j < 4; j++)
                    MMA(S[jb + j], kfl[kk][0], kfl[kk][1], kfl[kk][2], kfl[kk][3], QB0[p][j], QB1[p][j]);
            }
        }
    }

    // ================= softmax on S fragments (registers) =================
    u32 phi[16], plo[16];
    {
        float m0 = -1e30f, m1 = -1e30f;
#pragma unroll
        for (int j = 0; j < 8; j++) {
            m0 = fmaxf(m0, fmaxf(S[j][0], S[j][1]));
            m1 = fmaxf(m1, fmaxf(S[j][2], S[j][3]));
        }
        m0 = fmaxf(m0, __shfl_xor_sync(0xffffffffu, m0, 1));
        m0 = fmaxf(m0, __shfl_xor_sync(0xffffffffu, m0, 2));
        m1 = fmaxf(m1, __shfl_xor_sync(0xffffffffu, m1, 1));
        m1 = fmaxf(m1, __shfl_xor_sync(0xffffffffu, m1, 2));
        float s0 = 0.f, s1 = 0.f;
#pragma unroll
        for (int j = 0; j < 8; j++) {
            S[j][0] = __expf(S[j][0] - m0); S[j][1] = __expf(S[j][1] - m0);
            S[j][2] = __expf(S[j][2] - m1); S[j][3] = __expf(S[j][3] - m1);
            s0 += S[j][0] + S[j][1];
            s1 += S[j][2] + S[j][3];
        }
        s0 += __shfl_xor_sync(0xffffffffu, s0, 1);
        s0 += __shfl_xor_sync(0xffffffffu, s0, 2);
        s1 += __shfl_xor_sync(0xffffffffu, s1, 1);
        s1 += __shfl_xor_sync(0xffffffffu, s1, 2);
        float i0 = 1.f / s0, i1 = 1.f / s1;
#pragma unroll
        for (int j = 0; j < 8; j++) {
            split2(S[j][0] * i0, S[j][1] * i0, phi[2 * j], plo[2 * j]);
            split2(S[j][2] * i1, S[j][3] * i1, phi[2 * j + 1], plo[2 * j + 1]);
        }
    }

    // ================= phase B: V proj + O = P V + gate =================
    for (int cc = 0; cc < 4; cc++) {
        float acc[8][4];
#pragma unroll
        for (int j = 0; j < 8; j++) { acc[j][0] = acc[j][1] = acc[j][2] = acc[j][3] = 0.f; }
        RUNHALF(acc, 0);
        RUNHALF(acc, 4);
        {   // V epilogue: +bias, split, transposed swizzled store Vt[c][256B]
            char* vth = smc + QH_B;
            char* vtl = smc + QL_B;
            const float* bias = bv + cc * 64;
            int vu0 = R >> 3;
            int q2 = qd * 2;
#pragma unroll
            for (int j = 0; j < 8; j++) {
                float2 bb = *(const float2*)(bias + 8 * j + tq * 2);
                int c0 = 8 * j + tq * 2;
                float f0 = acc[j][0] + bb.x, f1 = acc[j][1] + bb.y;
                float f2 = acc[j][2] + bb.x, f3 = acc[j][3] + bb.y;
                u32 a00 = (u32)(c0 * 256 + ((vu0 ^ (c0 & 7)) << 4) + q2);
                u32 a10 = (u32)((c0 + 1) * 256 + ((vu0 ^ ((c0 + 1) & 7)) << 4) + q2);
                u32 a01 = (u32)(c0 * 256 + (((vu0 + 1) ^ (c0 & 7)) << 4) + q2);
                u32 a11 = (u32)((c0 + 1) * 256 + (((vu0 + 1) ^ ((c0 + 1) & 7)) << 4) + q2);
                __nv_bfloat16 h;
                h = __float2bfloat16(f0); *(__nv_bfloat16*)(vth + a00) = h;
                *(__nv_bfloat16*)(vtl + a00) = __float2bfloat16(f0 - __bfloat162float(h));
                h = __float2bfloat16(f1); *(__nv_bfloat16*)(vth + a10) = h;
                *(__nv_bfloat16*)(vtl + a10) = __float2bfloat16(f1 - __bfloat162float(h));
                h = __float2bfloat16(f2); *(__nv_bfloat16*)(vth + a01) = h;
                *(__nv_bfloat16*)(vtl + a01) = __float2bfloat16(f2 - __bfloat162float(h));
                h = __float2bfloat16(f3); *(__nv_bfloat16*)(vth + a11) = h;
                *(__nv_bfloat16*)(vtl + a11) = __float2bfloat16(f3 - __bfloat162float(h));
            }
        }
        __syncthreads();
        // ---- O = P * Vc (A = P regs, B = Vt smem; pipelined groups) ----
        float O[8][4];
#pragma unroll
        for (int j = 0; j < 8; j++) { O[j][0] = O[j][1] = O[j][2] = O[j][3] = 0.f; }
        {
            u32 VB0[2][4], VB1[2][4], VC0[2][4], VC1[2][4];
            {
                u32 ko = (u32)((0 ^ txe) << 4);
#pragma unroll
                for (int j = 0; j < 4; j++)
                    LDSM4(VB0[0][j], VB1[0][j], VC0[0][j], VC1[0][j], vAddrT + (u32)(j * 2048) + ko);
            }
#pragma unroll
            for (int g = 0; g < 8; g++) {     // g = kkv*2 + jg-half
                int p = g & 1, nx = p ^ 1;
                if (g < 7) {
                    int g2 = g + 1;
                    int kv2 = g2 >> 1, jb2 = (g2 & 1) * 4;
                    u32 ko2 = (u32)(((kv2 * 2) ^ txe) << 4);
#pragma unroll
                    for (int j = 0; j < 4; j++)
                        LDSM4(VB0[nx][j], VB1[nx][j], VC0[nx][j], VC1[nx][j],
                              vAddrT + (u32)((jb2 + j) * 2048) + ko2);
                }
                int kv = g >> 1, jb = (g & 1) * 4;
#pragma unroll
                for (int j = 0; j < 4; j++)
                    MMA(O[jb + j], phi[4 * kv], phi[4 * kv + 1], phi[4 * kv + 2], phi[4 * kv + 3], VB0[p][j], VB1[p][j]);
#pragma unroll
                for (int j = 0; j < 4; j++)
                    MMA(O[jb + j], phi[4 * kv], phi[4 * kv + 1], phi[4 * kv + 2], phi[4 * kv + 3], VC0[p][j], VC1[p][j]);
#pragma unroll
                for (int j = 0; j < 4; j++)
                    MMA(O[jb + j], plo[4 * kv], plo[4 * kv + 1], plo[4 * kv + 2], plo[4 * kv + 3], VB0[p][j], VB1[p][j]);
            }
        }
        // ---- gate with x, store ----
        {
            int r0 = R + qd;
#pragma unroll
            for (int j = 0; j < 8; j++) {
                int col = cc * 64 + 8 * j + tq * 2;
                float2 x0 = *(const float2*)(xg + r0 * 256 + col);
                float2 x1 = *(const float2*)(xg + (r0 + 8) * 256 + col);
                float2 o0 = make_float2(O[j][0] * x0.x, O[j][1] * x0.y);
                float2 o1 = make_float2(O[j][2] * x1.x, O[j][3] * x1.y);
                *(float2*)(og + r0 * 256 + col) = o0;
                *(float2*)(og + (r0 + 8) * 256 + col) = o1;
            }
        }
    }
}

extern "C" void kernel_launch(void* const* d_in, const int* in_sizes, int n_in,
                              void* d_out, int out_size)
{
    const float* x  = (const float*)d_in[0];
    const float* wq = (const float*)d_in[1];
    const float* bq = (const float*)d_in[2];
    const float* wk = (const float*)d_in[3];
    const float* bk = (const float*)d_in[4];
    const float* wv = (const float*)d_in[5];
    const float* bv = (const float*)d_in[6];
    float* out = (float*)d_out;

    prep_w<<<768, 256>>>(wq, wk, wv);

    int n_bh = in_sizes[0] / 16384;   // B*H = 2048
    cudaFuncSetAttribute(attn_mma_kernel,
                         cudaFuncAttributeMaxDynamicSharedMemorySize, SMEM_B);
    attn_mma_kernel<<<n_bh / 2, 256, SMEM_B>>>(x, bq, bk, bv, out);
}

// round 17
// speedup vs baseline: 1.0476x; 1.0476x over previous
#include <cuda_runtime.h>
#include <cuda_bf16.h>
#include <cstdint>

typedef uint32_t u32;

// Pre-split transposed weights: Wt[n][k] bf16 hi/lo, row-major [256][256] (512B rows).
__device__ __align__(16) unsigned char g_Wh[3][131072];
__device__ __align__(16) unsigned char g_Wl[3][131072];

// ---- smem byte map (regions XOR-swizzled: 16B-unit col ^= (row & 7)) ----
#define XH_B   0             // X hi [128 rows][512B]
#define WB_B   65536         // 4 W half-buffers (2 pair slots), each hi[32][512B]+lo[32][512B]=32K
#define QH_B   196608        // Q hi [128 rows][128B]   (phase B: Vt hi [64 rows][256B])
#define QL_B   212992        // Q lo                    (phase B: Vt lo)
#define SMEM_B 229376

#define MMA(d, a0, a1, a2, a3, b0, b1) \
    asm volatile("mma.sync.aligned.m16n8k16.row.col.f32.bf16.bf16.f32 " \
        "{%0,%1,%2,%3},{%4,%5,%6,%7},{%8,%9},{%0,%1,%2,%3};" \
        : "+f"((d)[0]), "+f"((d)[1]), "+f"((d)[2]), "+f"((d)[3]) \
        : "r"(a0), "r"(a1), "r"(a2), "r"(a3), "r"(b0), "r"(b1))

#define LDSM4(r0, r1, r2, r3, a) \
    asm volatile("ldmatrix.sync.aligned.m8n8.x4.shared.b16 {%0,%1,%2,%3}, [%4];" \
        : "=r"(r0), "=r"(r1), "=r"(r2), "=r"(r3) : "r"(a))

#define CPA16(dst, src) \
    asm volatile("cp.async.cg.shared.global [%0], [%1], 16;" :: "r"(dst), "l"(src))
#define CPC()  asm volatile("cp.async.commit_group;")
#define CPW1() asm volatile("cp.async.wait_group 1;")

__device__ __forceinline__ void split2(float f0, float f1, u32& hp, u32& lp) {
    asm("cvt.rn.bf16x2.f32 %0, %1, %2;" : "=r"(hp) : "f"(f1), "f"(f0));
    float h0 = __uint_as_float(hp << 16);
    float h1 = __uint_as_float(hp & 0xffff0000u);
    asm("cvt.rn.bf16x2.f32 %0, %1, %2;" : "=r"(lp) : "f"(f1 - h1), "f"(f0 - h0));
}

// ---------------- prep: transpose + split weights ----------------
__global__ void prep_w(const float* __restrict__ wq, const float* __restrict__ wk,
                       const float* __restrict__ wv)
{
    int idx = blockIdx.x * blockDim.x + threadIdx.x;
    if (idx >= 3 * 65536) return;
    int w = idx >> 16, e = idx & 65535;
    int k = e >> 8, n = e & 255;
    const float* W = (w == 0) ? wq : (w == 1) ? wk : wv;
    float f = W[k * 256 + n];
    __nv_bfloat16 h = __float2bfloat16(f);
    __nv_bfloat16 l = __float2bfloat16(f - __bfloat162float(h));
    *(__nv_bfloat16*)(g_Wh[w] + n * 512 + k * 2) = h;   // Wt[n][k]
    *(__nv_bfloat16*)(g_Wl[w] + n * 512 + k * 2) = l;
}

// prefetch one PAIR of half-chunks (2 x 32 n-rows, hi+lo) into a pair slot; one commit group.
// pairs 0..7 (phase A): cc = s>>1, h = s&1 -> (Wq rows, Wk rows) at row0 = cc*64 + h*32
// pairs 8..11 (phase B): cc = s-8 -> (Wv rows cc*64, Wv rows cc*64+32)
__device__ __forceinline__ void pf_pair(int s, u32 dA, int tid) {
    const unsigned char *gA, *lA, *gB, *lB;
    if (s < 8) {
        int row0 = (s >> 1) * 64 + (s & 1) * 32;
        gA = g_Wh[0] + row0 * 512; lA = g_Wl[0] + row0 * 512;
        gB = g_Wh[1] + row0 * 512; lB = g_Wl[1] + row0 * 512;
    } else {
        int row0 = (s - 8) * 64;
        gA = g_Wh[2] + row0 * 512;        lA = g_Wl[2] + row0 * 512;
        gB = g_Wh[2] + (row0 + 32) * 512; lB = g_Wl[2] + (row0 + 32) * 512;
    }
    u32 dB = dA + 32768;
#pragma unroll
    for (int i = 0; i < 4; i++) {
        int e = tid + i * 256;               // 0..1023: 32 rows x 32 units
        int r = e >> 5, c = e & 31;
        u32 so = (u32)(r * 512 + ((c ^ (r & 7)) << 4));
        u32 co = (u32)(r * 512 + c * 16);
        CPA16(dA + so, gA + co);
        CPA16(dA + 16384 + so, lA + co);
        CPA16(dB + so, gB + co);
        CPA16(dB + 16384 + so, lB + co);
    }
    CPC();
}

// fused pair pass: shared A fragments, two independent accumulator families.
#define RUNPAIR(ACCA, ACCB, WA, WB) do {                                        \
    _Pragma("unroll")                                                           \
    for (int kk = 0; kk < 16; kk++) {                                           \
        u32 koff = (u32)(((kk * 2) ^ txe) << 4);                                \
        u32 ah0, ah1, ah2, ah3;                                                 \
        LDSM4(ah0, ah1, ah2, ah3, aXH + koff);                                  \
        u32 AB0[4], AB1[4], AC0[4], AC1[4];                                     \
        u32 BB0[4], BB1[4], BC0[4], BC1[4];                                     \
        _Pragma("unroll")                                                       \
        for (int j = 0; j < 4; j++)                                             \
            LDSM4(AB0[j], AB1[j], AC0[j], AC1[j], (WA) + (u32)(j * 4096) + koff); \
        _Pragma("unroll")                                                       \
        for (int j = 0; j < 4; j++)                                             \
            LDSM4(BB0[j], BB1[j], BC0[j], BC1[j], (WB) + (u32)(j * 4096) + koff); \
        _Pragma("unroll")                                                       \
        for (int j = 0; j < 4; j++)                                             \
            MMA((ACCA)[j], ah0, ah1, ah2, ah3, AB0[j], AB1[j]);                 \
        _Pragma("unroll")                                                       \
        for (int j = 0; j < 4; j++)                                             \
            MMA((ACCB)[j], ah0, ah1, ah2, ah3, BB0[j], BB1[j]);                 \
        _Pragma("unroll")                                                       \
        for (int j = 0; j < 4; j++)                                             \
            MMA((ACCA)[j], alo[kk][0], alo[kk][1], alo[kk][2], alo[kk][3], AB0[j], AB1[j]); \
        _Pragma("unroll")                                                       \
        for (int j = 0; j < 4; j++)                                             \
            MMA((ACCB)[j], alo[kk][0], alo[kk][1], alo[kk][2], alo[kk][3], BB0[j], BB1[j]); \
        _Pragma("unroll")                                                       \
        for (int j = 0; j < 4; j++)                                             \
            MMA((ACCA)[j], ah0, ah1, ah2, ah3, AC0[j], AC1[j]);                 \
        _Pragma("unroll")                                                       \
        for (int j = 0; j < 4; j++)                                             \
            MMA((ACCB)[j], ah0, ah1, ah2, ah3, BC0[j], BC1[j]);                 \
    }                                                                           \
} while (0)

// one pipeline stage: wait pair, consume, then prefetch pair+2 into this slot.
#define STAGE(ACCA, ACCB) do {                                                  \
    CPW1(); __syncthreads();                                                    \
    u32 _wa = wAddrT + (u32)((stage & 1) * 65536);                              \
    RUNPAIR(ACCA, ACCB, _wa, _wa + 32768);                                      \
    __syncthreads();                                                            \
    if (stage + 2 < 12) pf_pair(stage + 2, smb + WB_B + (u32)((stage & 1) * 65536), tid); \
    else CPC();                                                                 \
    stage++;                                                                    \
} while (0)

__global__ void __launch_bounds__(256, 1)
attn_mma_kernel(const float* __restrict__ x,
                const float* __restrict__ bq, const float* __restrict__ bk,
                const float* __restrict__ bv, float* __restrict__ out)
{
    extern __shared__ char smc[];
    u32 smb;
    asm("{ .reg .u64 t; cvta.to.shared.u64 t, %1; cvt.u32.u64 %0, t; }" : "=r"(smb) : "l"(smc));

    const int tid = threadIdx.x;
    const int w = tid >> 5, t = tid & 31;
    const int qd = t >> 2, tq = t & 3;
    const int R = w * 16;                 // warp's 16 stacked rows
    const int bh64 = (w >> 2) * 64;       // 0 (bh0) or 64 (bh1)

    // ldmatrix thread-role decomposition
    const int tm8 = t & 7;
    const int g8  = (t >> 3) & 1;
    const int g16 = t >> 4;
    const int txe = tm8 & 6, txo = tm8 & 1;

    const float* xg = x + (size_t)blockIdx.x * 32768;
    float*       og = out + (size_t)blockIdx.x * 32768;

    u32* qh = (u32*)(smc + QH_B);
    u32* ql = (u32*)(smc + QL_B);

    // ---- stage X: hi -> XH, lo -> WB region (temp), both swizzled ----
    {
        int row = tid >> 1, khf = (tid & 1) * 128;
        const float4* src = (const float4*)(xg + row * 256 + khf);
        int rx = row & 7;
        char* dh = smc + XH_B + row * 512;
        char* dl = smc + WB_B + row * 512;
#pragma unroll 8
        for (int j2 = 0; j2 < 32; j2++) {
            float4 v = src[j2];
            int unit = (khf >> 3) + (j2 >> 1);
            u32 off = (u32)(((unit ^ rx) << 4) + ((j2 & 1) << 3));
            u32 h0, l0, h1, l1;
            split2(v.x, v.y, h0, l0);
            split2(v.z, v.w, h1, l1);
            *(u32*)(dh + off) = h0; *(u32*)(dh + off + 4) = h1;
            *(u32*)(dl + off) = l0; *(u32*)(dl + off + 4) = l1;
        }
    }
    __syncthreads();

    // ---- A-lo fragments -> registers via ldmatrix ----
    const u32 aXH = smb + XH_B + (u32)(R + tm8 + 8 * g8) * 512 + (u32)((g16 ^ txo) << 4);
    u32 alo[16][4];
    {
        const u32 aXLt = smb + WB_B + (u32)(R + tm8 + 8 * g8) * 512 + (u32)((g16 ^ txo) << 4);
#pragma unroll
        for (int kk = 0; kk < 16; kk++) {
            u32 koff = (u32)(((kk * 2) ^ txe) << 4);
            LDSM4(alo[kk][0], alo[kk][1], alo[kk][2], alo[kk][3], aXLt + koff);
        }
    }
    __syncthreads();

    // ---- per-thread ldmatrix base addresses ----
    const u32 wAddrT = smb + WB_B + (u32)g16 * 16384 + (u32)tm8 * 512 + (u32)((g8 ^ txo) << 4);
    const u32 qAddrT = smb + QH_B + (u32)g16 * 16384 + (u32)(bh64 + tm8) * 128 + (u32)((g8 ^ txo) << 4);
    const u32 vAddrT = smb + QH_B + (u32)g16 * 16384 + (u32)tm8 * 256 + (u32)((bh64 >> 3) << 4) + (u32)((g8 ^ txo) << 4);

    // ---- prime the W pair pipeline (2 pair slots) ----
    pf_pair(0, smb + WB_B, tid);
    pf_pair(1, smb + WB_B + 65536, tid);
    int stage = 0;

    float S[8][4];
#pragma unroll
    for (int j = 0; j < 8; j++) { S[j][0] = S[j][1] = S[j][2] = S[j][3] = 0.f; }

    // ================= phase A: fused Q+K proj + S accumulation =================
    for (int cc = 0; cc < 4; cc++) {
        float accQ[8][4], accK[8][4];
        u32 khi[16], klo[16];
#pragma unroll
        for (int j = 0; j < 8; j++) {
            accQ[j][0] = accQ[j][1] = accQ[j][2] = accQ[j][3] = 0.f;
            accK[j][0] = accK[j][1] = accK[j][2] = accK[j][3] = 0.f;
        }
        STAGE(accQ, accK);          // n-cols 0..31 of chunk
        STAGE(accQ + 4, accK + 4);  // n-cols 32..63
        {   // Q epilogue: +bias, split, swizzled store [row][128B]
            const float* bias = bq + cc * 64;
            int r0 = R + qd;
#pragma unroll
            for (int j = 0; j < 8; j++) {
                float2 bb = *(const float2*)(bias + 8 * j + tq * 2);
                int wo = ((j ^ qd) << 2) + tq;
                u32 hp, lp;
                split2(accQ[j][0] + bb.x, accQ[j][1] + bb.y, hp, lp);
                qh[r0 * 32 + wo] = hp; ql[r0 * 32 + wo] = lp;
                split2(accQ[j][2] + bb.x, accQ[j][3] + bb.y, hp, lp);
                qh[(r0 + 8) * 32 + wo] = hp; ql[(r0 + 8) * 32 + wo] = lp;
            }
        }
        {   // K epilogue: +bias, split -> registers
            const float* bias = bk + cc * 64;
#pragma unroll
            for (int j = 0; j < 8; j++) {
                float2 bb = *(const float2*)(bias + 8 * j + tq * 2);
                split2(accK[j][0] + bb.x, accK[j][1] + bb.y, khi[2 * j], klo[2 * j]);
                split2(accK[j][2] + bb.x, accK[j][3] + bb.y, khi[2 * j + 1], klo[2 * j + 1]);
            }
        }
        __syncthreads();   // Q visible to all warps
        // ---- S += Kc * Qc^T  (A = K regs, B = Q smem; term-major, groups of 4) ----
#pragma unroll
        for (int kk = 0; kk < 4; kk++) {
            u32 koff = (u32)(((kk * 2) ^ txe) << 4);
#pragma unroll
            for (int jg = 0; jg < 8; jg += 4) {
                u32 B0[4], B1[4], C0[4], C1[4];
#pragma unroll
                for (int j = 0; j < 4; j++)
                    LDSM4(B0[j], B1[j], C0[j], C1[j], qAddrT + (u32)((jg + j) * 1024) + koff);
#pragma unroll
                for (int j = 0; j < 4; j++)
                    MMA(S[jg + j], khi[4 * kk], khi[4 * kk + 1], khi[4 * kk + 2], khi[4 * kk + 3], B0[j], B1[j]);
#pragma unroll
                for (int j = 0; j < 4; j++)
                    MMA(S[jg + j], khi[4 * kk], khi[4 * kk + 1], khi[4 * kk + 2], khi[4 * kk + 3], C0[j], C1[j]);
#pragma unroll
                for (int j = 0; j < 4; j++)
                    MMA(S[jg + j], klo[4 * kk], klo[4 * kk + 1], klo[4 * kk + 2], klo[4 * kk + 3], B0[j], B1[j]);
            }
        }
    }

    // ================= softmax on S fragments (registers) =================
    u32 phi[16], plo[16];
    {
        float m0 = -1e30f, m1 = -1e30f;
#pragma unroll
        for (int j = 0; j < 8; j++) {
            m0 = fmaxf(m0, fmaxf(S[j][0], S[j][1]));
            m1 = fmaxf(m1, fmaxf(S[j][2], S[j][3]));
        }
        m0 = fmaxf(m0, __shfl_xor_sync(0xffffffffu, m0, 1));
        m0 = fmaxf(m0, __shfl_xor_sync(0xffffffffu, m0, 2));
        m1 = fmaxf(m1, __shfl_xor_sync(0xffffffffu, m1, 1));
        m1 = fmaxf(m1, __shfl_xor_sync(0xffffffffu, m1, 2));
        float s0 = 0.f, s1 = 0.f;
#pragma unroll
        for (int j = 0; j < 8; j++) {
            S[j][0] = __expf(S[j][0] - m0); S[j][1] = __expf(S[j][1] - m0);
            S[j][2] = __expf(S[j][2] - m1); S[j][3] = __expf(S[j][3] - m1);
            s0 += S[j][0] + S[j][1];
            s1 += S[j][2] + S[j][3];
        }
        s0 += __shfl_xor_sync(0xffffffffu, s0, 1);
        s0 += __shfl_xor_sync(0xffffffffu, s0, 2);
        s1 += __shfl_xor_sync(0xffffffffu, s1, 1);
        s1 += __shfl_xor_sync(0xffffffffu, s1, 2);
        float i0 = 1.f / s0, i1 = 1.f / s1;
#pragma unroll
        for (int j = 0; j < 8; j++) {
            split2(S[j][0] * i0, S[j][1] * i0, phi[2 * j], plo[2 * j]);
            split2(S[j][2] * i1, S[j][3] * i1, phi[2 * j + 1], plo[2 * j + 1]);
        }
    }

    // ================= phase B: V proj (paired halves) + O = P V + gate =================
    for (int cc = 0; cc < 4; cc++) {
        float accV[8][4];
#pragma unroll
        for (int j = 0; j < 8; j++) { accV[j][0] = accV[j][1] = accV[j][2] = accV[j][3] = 0.f; }
        STAGE(accV, accV + 4);      // bufA -> n 0..31, bufB -> n 32..63
        {   // V epilogue: +bias, split, transposed swizzled store Vt[c][256B]
            char* vth = smc + QH_B;
            char* vtl = smc + QL_B;
            const float* bias = bv + cc * 64;
            int vu0 = R >> 3;
            int q2 = qd * 2;
#pragma unroll
            for (int j = 0; j < 8; j++) {
                float2 bb = *(const float2*)(bias + 8 * j + tq * 2);
                int c0 = 8 * j + tq * 2;
                float f0 = accV[j][0] + bb.x, f1 = accV[j][1] + bb.y;
                float f2 = accV[j][2] + bb.x, f3 = accV[j][3] + bb.y;
                u32 a00 = (u32)(c0 * 256 + ((vu0 ^ (c0 & 7)) << 4) + q2);
                u32 a10 = (u32)((c0 + 1) * 256 + ((vu0 ^ ((c0 + 1) & 7)) << 4) + q2);
                u32 a01 = (u32)(c0 * 256 + (((vu0 + 1) ^ (c0 & 7)) << 4) + q2);
                u32 a11 = (u32)((c0 + 1) * 256 + (((vu0 + 1) ^ ((c0 + 1) & 7)) << 4) + q2);
                __nv_bfloat16 h;
                h = __float2bfloat16(f0); *(__nv_bfloat16*)(vth + a00) = h;
                *(__nv_bfloat16*)(vtl + a00) = __float2bfloat16(f0 - __bfloat162float(h));
                h = __float2bfloat16(f1); *(__nv_bfloat16*)(vth + a10) = h;
                *(__nv_bfloat16*)(vtl + a10) = __float2bfloat16(f1 - __bfloat162float(h));
                h = __float2bfloat16(f2); *(__nv_bfloat16*)(vth + a01) = h;
                *(__nv_bfloat16*)(vtl + a01) = __float2bfloat16(f2 - __bfloat162float(h));
                h = __float2bfloat16(f3); *(__nv_bfloat16*)(vth + a11) = h;
                *(__nv_bfloat16*)(vtl + a11) = __float2bfloat16(f3 - __bfloat162float(h));
            }
        }
        __syncthreads();
        // ---- O = P * Vc (A = P regs, B = Vt smem; term-major, groups of 4) ----
        float O[8][4];
#pragma unroll
        for (int j = 0; j < 8; j++) { O[j][0] = O[j][1] = O[j][2] = O[j][3] = 0.f; }
#pragma unroll
        for (int kkv = 0; kkv < 4; kkv++) {
            u32 koff = (u32)(((kkv * 2) ^ txe) << 4);
#pragma unroll
            for (int jg = 0; jg < 8; jg += 4) {
                u32 B0[4], B1[4], C0[4], C1[4];
#pragma unroll
                for (int j = 0; j < 4; j++)
                    LDSM4(B0[j], B1[j], C0[j], C1[j], vAddrT + (u32)((jg + j) * 2048) + koff);
#pragma unroll
                for (int j = 0; j < 4; j++)
                    MMA(O[jg + j], phi[4 * kkv], phi[4 * kkv + 1], phi[4 * kkv + 2], phi[4 * kkv + 3], B0[j], B1[j]);
#pragma unroll
                for (int j = 0; j < 4; j++)
                    MMA(O[jg + j], phi[4 * kkv], phi[4 * kkv + 1], phi[4 * kkv + 2], phi[4 * kkv + 3], C0[j], C1[j]);
#pragma unroll
                for (int j = 0; j < 4; j++)
                    MMA(O[jg + j], plo[4 * kkv], plo[4 * kkv + 1], plo[4 * kkv + 2], plo[4 * kkv + 3], B0[j], B1[j]);
            }
        }
        // ---- gate with x, store ----
        {
            int r0 = R + qd;
#pragma unroll
            for (int j = 0; j < 8; j++) {
                int col = cc * 64 + 8 * j + tq * 2;
                float2 x0 = *(const float2*)(xg + r0 * 256 + col);
                float2 x1 = *(const float2*)(xg + (r0 + 8) * 256 + col);
                float2 o0 = make_float2(O[j][0] * x0.x, O[j][1] * x0.y);
                float2 o1 = make_float2(O[j][2] * x1.x, O[j][3] * x1.y);
                *(float2*)(og + r0 * 256 + col) = o0;
                *(float2*)(og + (r0 + 8) * 256 + col) = o1;
            }
        }
    }
}

extern "C" void kernel_launch(void* const* d_in, const int* in_sizes, int n_in,
                              void* d_out, int out_size)
{
    const float* x  = (const float*)d_in[0];
    const float* wq = (const float*)d_in[1];
    const float* bq = (const float*)d_in[2];
    const float* wk = (const float*)d_in[3];
    const float* bk = (const float*)d_in[4];
    const float* wv = (const float*)d_in[5];
    const float* bv = (const float*)d_in[6];
    float* out = (float*)d_out;

    prep_w<<<768, 256>>>(wq, wk, wv);

    int n_bh = in_sizes[0] / 16384;   // B*H = 2048
    cudaFuncSetAttribute(attn_mma_kernel,
                         cudaFuncAttributeMaxDynamicSharedMemorySize, SMEM_B);
    attn_mma_kernel<<<n_bh / 2, 256, SMEM_B>>>(x, bq, bk, bv, out);
}